// round 3
// baseline (speedup 1.0000x reference)
#include <cuda_runtime.h>
#include <math.h>

#define BB   32
#define TT   400
#define MELD 80
#define LLd  256
#define UU   512
#define MMa  200
#define U4   2048
#define U3   1536
#define BT   (BB*TT)      // 12800
#define NBLK 148
#define NTHR 1024

// ---------------- scratch (device globals: allocation-free) ----------------
__device__ float g_inT [BT*MELD];          // inputs transposed to [T,B,80]
__device__ float g_h1  [BT*UU];            // prenet hidden
__device__ float g_xp  [BT*LLd];           // prenet out [T,B,256]
__device__ float g_keys[BB*MMa*UU];        // attention keys
__device__ float g_xpart[(size_t)BT*U4];   // xp @ lstm_K[:256] + lstm_b
__device__ float g_x   [BT*UU];            // LSTM outputs [T,B,512]
__device__ float g_y1  [BT*UU];            // GRU1 outputs
__device__ float g_xsum[BT*UU];            // x+y1 then x+y1+y2
__device__ float g_xz  [(size_t)BT*U3];    // GRU input projection (reused)
__device__ float g_hstate[BB*UU];
__device__ float g_cstate[BB*UU];
__device__ float g_rec [BB*U4];
__device__ float g_ctx [BB*LLd];
__device__ unsigned g_cnt = 0;
__device__ unsigned g_gen = 0;

// ---------------- software grid barrier ----------------
__device__ __forceinline__ void grid_barrier(unsigned nb)
{
    __syncthreads();
    if (threadIdx.x == 0) {
        __threadfence();
        unsigned my   = atomicAdd(&g_gen, 0u);     // coherent read of generation
        unsigned prev = atomicAdd(&g_cnt, 1u);
        if (prev == nb - 1u) {
            atomicExch(&g_cnt, 0u);
            __threadfence();
            atomicAdd(&g_gen, 1u);
        } else {
            while (atomicAdd(&g_gen, 0u) == my) { __nanosleep(64); }
        }
        __threadfence();
    }
    __syncthreads();
}

__device__ __forceinline__ float sigmoidf_(float x) { return 1.f / (1.f + expf(-x)); }

// ---------------- repack inputs [B,T,80] -> [T,B,80] ----------------
__global__ void repack_inputs(const float* __restrict__ in)
{
    int i = blockIdx.x * blockDim.x + threadIdx.x;
    if (i < BT * MELD) {
        int d = i % MELD;
        int r = i / MELD;          // r = t*32 + b
        int t = r >> 5, b = r & 31;
        g_inT[i] = in[((size_t)b * TT + t) * MELD + d];
    }
}

// ---------------- elementwise add: xsum = x + y1 ----------------
__global__ void add_kernel()
{
    int i = blockIdx.x * blockDim.x + threadIdx.x;
    if (i < BT * UU) g_xsum[i] = g_x[i] + g_y1[i];
}

// ---------------- generic tiled fp32 GEMM: C = op(A[M,K] @ W[K,N] + bias) ----------------
__global__ void gemm_tiled(const float* __restrict__ A, const float* __restrict__ W,
                           const float* __restrict__ bias, float* __restrict__ C,
                           int Mr, int N, int K, int doRelu, int remapTB)
{
    __shared__ float As[16][65];
    __shared__ float Bs[16][64];
    const int tid = threadIdx.x;
    const int tx = tid & 15, ty = tid >> 4;
    const int n0 = blockIdx.x * 64, m0 = blockIdx.y * 64;
    float acc[4][4] = {};

    for (int k0 = 0; k0 < K; k0 += 16) {
#pragma unroll
        for (int i = 0; i < 4; i++) {
            int e = tid + i * 256;
            int r = e >> 4, c = e & 15;
            int gr = m0 + r, gc = k0 + c;
            As[c][r] = (gr < Mr && gc < K) ? A[(size_t)gr * K + gc] : 0.f;
        }
#pragma unroll
        for (int i = 0; i < 4; i++) {
            int e = tid + i * 256;
            int r = e >> 6, c = e & 63;
            int gk = k0 + r, gn = n0 + c;
            Bs[r][c] = (gk < K && gn < N) ? W[(size_t)gk * N + gn] : 0.f;
        }
        __syncthreads();
#pragma unroll
        for (int kk = 0; kk < 16; kk++) {
            float a0 = As[kk][ty*4+0], a1 = As[kk][ty*4+1];
            float a2 = As[kk][ty*4+2], a3 = As[kk][ty*4+3];
            float4 b4 = *(const float4*)&Bs[kk][tx*4];
            acc[0][0] += a0*b4.x; acc[0][1] += a0*b4.y; acc[0][2] += a0*b4.z; acc[0][3] += a0*b4.w;
            acc[1][0] += a1*b4.x; acc[1][1] += a1*b4.y; acc[1][2] += a1*b4.z; acc[1][3] += a1*b4.w;
            acc[2][0] += a2*b4.x; acc[2][1] += a2*b4.y; acc[2][2] += a2*b4.z; acc[2][3] += a2*b4.w;
            acc[3][0] += a3*b4.x; acc[3][1] += a3*b4.y; acc[3][2] += a3*b4.z; acc[3][3] += a3*b4.w;
        }
        __syncthreads();
    }
#pragma unroll
    for (int i = 0; i < 4; i++) {
        int row = m0 + ty*4 + i;
        if (row >= Mr) continue;
#pragma unroll
        for (int j = 0; j < 4; j++) {
            int col = n0 + tx*4 + j;
            if (col >= N) continue;
            float v = acc[i][j] + (bias ? __ldg(bias + col) : 0.f);
            if (doRelu) v = fmaxf(v, 0.f);
            size_t oi;
            if (remapTB) { int t = row >> 5, b = row & 31; oi = ((size_t)b * TT + t) * N + col; }
            else         { oi = (size_t)row * N + col; }
            C[oi] = v;
        }
    }
}

// ---------------- persistent attention-LSTM ----------------
__global__ void __launch_bounds__(NTHR) lstm_attn(
    const float* __restrict__ attended,
    const float* __restrict__ qW, const float* __restrict__ qb,
    const float* __restrict__ vW, const float* __restrict__ vb,
    const float* __restrict__ lstmK, const float* __restrict__ lstmR)
{
    const int tid = threadIdx.x, bid = blockIdx.x;
    __shared__ float h_s[UU];
    __shared__ float q_s[UU];
    __shared__ float v_s[UU];
    __shared__ float qp[NTHR];
    __shared__ float sc[256];
    __shared__ float red[256];
    __shared__ float ctxp[NTHR];
    __shared__ float ctx_s[LLd];
    __shared__ float part[NTHR];
    __shared__ float zz[UU];

    // zero LSTM state
    for (int i = bid * NTHR + tid; i < BB * UU; i += NBLK * NTHR) {
        g_hstate[i] = 0.f; g_cstate[i] = 0.f;
    }
    grid_barrier(NBLK);

    for (int t = 0; t < TT; ++t) {
        // ---- stage 1: attention (blocks 0..31) || rec = h@R + xpart (blocks 32..95) ----
        if (bid < BB) {
            const int b = bid;
            if (tid < UU) { h_s[tid] = __ldcg(&g_hstate[b*UU + tid]); v_s[tid] = __ldg(vW + tid); }
            __syncthreads();
            // q = h @ Wq + qb   (split-k over 2 halves, 1024 threads)
            {
                int u = tid & (UU - 1);
                int half = tid >> 9;
                const float* w = qW + (size_t)(half * 256) * UU + u;
                float acc = 0.f;
#pragma unroll 8
                for (int k = 0; k < 256; ++k) acc += h_s[half*256 + k] * __ldg(w + (size_t)k * UU);
                qp[half*UU + u] = acc;
            }
            __syncthreads();
            if (tid < UU) q_s[tid] = qp[tid] + qp[UU + tid] + __ldg(qb + tid);
            __syncthreads();
            // scores: warp per m
            {
                int w = tid >> 5, lane = tid & 31;
                for (int m = w; m < MMa; m += 32) {
                    const float* krow = g_keys + ((size_t)(b*MMa + m)) * UU;
                    float acc = 0.f;
#pragma unroll
                    for (int j = 0; j < UU/32; ++j) {
                        int u = lane + 32*j;
                        acc += v_s[u] * tanhf(__ldg(krow + u) + q_s[u]);
                    }
                    for (int o = 16; o > 0; o >>= 1) acc += __shfl_down_sync(0xffffffffu, acc, o);
                    if (lane == 0) sc[m] = acc + __ldg(vb);
                }
            }
            __syncthreads();
            // softmax over 200
            if (tid < 256) red[tid] = (tid < MMa) ? sc[tid] : -1e30f;
            __syncthreads();
            for (int s = 128; s > 0; s >>= 1) { if (tid < s) red[tid] = fmaxf(red[tid], red[tid+s]); __syncthreads(); }
            float mx = red[0];
            __syncthreads();
            if (tid < 256) { float e = (tid < MMa) ? expf(sc[tid] - mx) : 0.f; sc[tid] = e; red[tid] = e; }
            __syncthreads();
            for (int s = 128; s > 0; s >>= 1) { if (tid < s) red[tid] += red[tid+s]; __syncthreads(); }
            float inv = 1.f / red[0];
            // ctx = attn @ attended   (4 m-partitions x 256 dims)
            {
                int d = tid & (LLd - 1);
                int prt = tid >> 8;               // 0..3
                const float* att = attended + ((size_t)b * MMa) * LLd + d;
                float acc = 0.f;
                int m0 = prt * 50;
                for (int m = m0; m < m0 + 50; ++m) acc += sc[m] * __ldg(att + (size_t)m * LLd);
                ctxp[tid] = acc;
            }
            __syncthreads();
            if (tid < LLd)
                g_ctx[b*LLd + tid] = (ctxp[tid] + ctxp[LLd+tid] + ctxp[2*LLd+tid] + ctxp[3*LLd+tid]) * inv;
        } else if (bid < BB + 64) {
            const int unit = bid - BB;
            const int b = unit >> 1, nh = unit & 1;
            if (tid < UU) h_s[tid] = __ldcg(&g_hstate[b*UU + tid]);
            __syncthreads();
            int n = nh * 1024 + tid;
            float s = g_xpart[(size_t)t * (BB*U4) + (size_t)b * U4 + n];
            const float* R = lstmR + n;
#pragma unroll 8
            for (int k = 0; k < UU; ++k) s += h_s[k] * __ldg(R + (size_t)k * U4);
            g_rec[b*U4 + n] = s;
        }
        grid_barrier(NBLK);

        // ---- stage 2: z = rec + ctx@K2 -> gates -> h,c ----
        if (bid < 128) {
            const int b = bid >> 2, c = bid & 3;
            if (tid < LLd) ctx_s[tid] = __ldcg(&g_ctx[b*LLd + tid]);
            __syncthreads();
            const float* K2 = lstmK + (size_t)LLd * U4;  // rows 256..511
            {
                int half = tid >> 9;
                int dotid = tid & 511;
                int g = dotid >> 7, up = dotid & 127;
                int n = g*UU + c*128 + up;
                const float* w = K2 + (size_t)(half * 128) * U4 + n;
                float acc = 0.f;
#pragma unroll 8
                for (int d = 0; d < 128; ++d) acc += ctx_s[half*128 + d] * __ldg(w + (size_t)d * U4);
                part[tid] = acc;
            }
            __syncthreads();
            if (tid < UU) {
                int g = tid >> 7, up = tid & 127;
                int n = g*UU + c*128 + up;
                zz[tid] = part[tid] + part[UU + tid] + __ldcg(&g_rec[b*U4 + n]);
            }
            __syncthreads();
            if (tid < 128) {
                int u = c*128 + tid;
                float ig = sigmoidf_(zz[tid]);
                float fg = sigmoidf_(zz[128 + tid]);
                float gg = tanhf   (zz[256 + tid]);
                float og = sigmoidf_(zz[384 + tid]);
                float cold = __ldcg(&g_cstate[b*UU + u]);
                float cn = fg * cold + ig * gg;
                float hn = og * tanhf(cn);
                g_cstate[b*UU + u] = cn;
                g_hstate[b*UU + u] = hn;
                g_x[((size_t)t*BB + b)*UU + u] = hn;
            }
        }
        grid_barrier(NBLK);
    }
}

// ---------------- persistent GRU (reset_after=True) ----------------
__global__ void __launch_bounds__(NTHR) gru_seq(
    const float* __restrict__ R, const float* __restrict__ br,
    const float* __restrict__ xz, float* __restrict__ yout, int accumulate)
{
    const int tid = threadIdx.x, bid = blockIdx.x;
    __shared__ float h_s[UU];
    __shared__ float part[768];
    __shared__ float rec_s[384];

    for (int i = bid * NTHR + tid; i < BB * UU; i += NBLK * NTHR) g_hstate[i] = 0.f;
    grid_barrier(NBLK);

    for (int t = 0; t < TT; ++t) {
        if (bid < 128) {
            const int b = bid >> 2, c = bid & 3;
            if (tid < UU) h_s[tid] = __ldcg(&g_hstate[b*UU + tid]);
            __syncthreads();
            if (tid < 768) {
                int half = (tid >= 384) ? 1 : 0;
                int dotid = tid - half * 384;
                int g = dotid >> 7, up = dotid & 127;
                int n = g*UU + c*128 + up;
                const float* w = R + (size_t)(half * 256) * U3 + n;
                float acc = 0.f;
#pragma unroll 8
                for (int k = 0; k < 256; ++k) acc += h_s[half*256 + k] * __ldg(w + (size_t)k * U3);
                part[tid] = acc;
            }
            __syncthreads();
            if (tid < 384) {
                int g = tid >> 7, up = tid & 127;
                int n = g*UU + c*128 + up;
                rec_s[tid] = part[tid] + part[384 + tid] + __ldg(br + n);
            }
            __syncthreads();
            if (tid < 128) {
                int u = c*128 + tid;
                const float* xzr = xz + ((size_t)t*BB + b) * U3;
                float xz_z = __ldg(xzr + u);
                float xz_r = __ldg(xzr + UU + u);
                float xz_h = __ldg(xzr + 2*UU + u);
                float z = sigmoidf_(xz_z + rec_s[tid]);
                float r = sigmoidf_(xz_r + rec_s[128 + tid]);
                float hh = tanhf(xz_h + r * rec_s[256 + tid]);
                float hn = z * h_s[u] + (1.f - z) * hh;
                g_hstate[b*UU + u] = hn;
                size_t oi = ((size_t)t*BB + b)*UU + u;
                if (accumulate) yout[oi] += hn; else yout[oi] = hn;
            }
        }
        grid_barrier(NBLK);
    }
}

// ---------------- launch ----------------
extern "C" void kernel_launch(void* const* d_in, const int* in_sizes, int n_in,
                              void* d_out, int out_size)
{
    const float* inputs   = (const float*)d_in[0];
    const float* attended = (const float*)d_in[1];
    const float* pre_W1   = (const float*)d_in[2];
    const float* pre_b1   = (const float*)d_in[3];
    const float* pre_W2   = (const float*)d_in[4];
    const float* pre_b2   = (const float*)d_in[5];
    const float* key_W    = (const float*)d_in[6];
    const float* key_b    = (const float*)d_in[7];
    const float* query_W  = (const float*)d_in[8];
    const float* query_b  = (const float*)d_in[9];
    const float* attnv_W  = (const float*)d_in[10];
    const float* attnv_b  = (const float*)d_in[11];
    const float* lstm_K   = (const float*)d_in[12];
    const float* lstm_R   = (const float*)d_in[13];
    const float* lstm_b   = (const float*)d_in[14];
    const float* gru1_K   = (const float*)d_in[15];
    const float* gru1_R   = (const float*)d_in[16];
    const float* gru1_b   = (const float*)d_in[17];
    const float* gru2_K   = (const float*)d_in[18];
    const float* gru2_R   = (const float*)d_in[19];
    const float* gru2_b   = (const float*)d_in[20];
    const float* proj_W   = (const float*)d_in[21];
    float* out = (float*)d_out;

    float *inT, *h1, *xp, *keys, *xpart, *x, *y1, *xsum, *xz;
    cudaGetSymbolAddress((void**)&inT,   g_inT);
    cudaGetSymbolAddress((void**)&h1,    g_h1);
    cudaGetSymbolAddress((void**)&xp,    g_xp);
    cudaGetSymbolAddress((void**)&keys,  g_keys);
    cudaGetSymbolAddress((void**)&xpart, g_xpart);
    cudaGetSymbolAddress((void**)&x,     g_x);
    cudaGetSymbolAddress((void**)&y1,    g_y1);
    cudaGetSymbolAddress((void**)&xsum,  g_xsum);
    cudaGetSymbolAddress((void**)&xz,    g_xz);

    // 1) repack inputs to [T,B,80]
    repack_inputs<<<(BT*MELD + 255)/256, 256>>>(inputs);
    // 2) prenet
    gemm_tiled<<<dim3(UU/64,  BT/64), 256>>>(inT, pre_W1, pre_b1, h1, BT, UU, MELD, 1, 0);
    gemm_tiled<<<dim3(LLd/64, BT/64), 256>>>(h1,  pre_W2, pre_b2, xp, BT, LLd, UU,  1, 0);
    // 3) keys
    gemm_tiled<<<dim3(UU/64, (BB*MMa)/64), 256>>>(attended, key_W, key_b, keys, BB*MMa, UU, LLd, 0, 0);
    // 4) LSTM input part: xp @ lstm_K[:256] + lstm_b
    gemm_tiled<<<dim3(U4/64, BT/64), 256>>>(xp, lstm_K, lstm_b, xpart, BT, U4, LLd, 0, 0);
    // 5) attention LSTM (persistent)
    lstm_attn<<<NBLK, NTHR>>>(attended, query_W, query_b, attnv_W, attnv_b, lstm_K, lstm_R);
    // 6) GRU1: xz = x @ gru1_K + bi1 ; recurrence
    gemm_tiled<<<dim3(U3/64, BT/64), 256>>>(x, gru1_K, gru1_b, xz, BT, U3, UU, 0, 0);
    gru_seq<<<NBLK, NTHR>>>(gru1_R, gru1_b + U3, xz, y1, 0);
    // 7) xsum = x + y1
    add_kernel<<<(BT*UU + 255)/256, 256>>>();
    // 8) GRU2 on xsum, accumulate y2 into xsum
    gemm_tiled<<<dim3(U3/64, BT/64), 256>>>(xsum, gru2_K, gru2_b, xz, BT, U3, UU, 0, 0);
    gru_seq<<<NBLK, NTHR>>>(gru2_R, gru2_b + U3, xz, xsum, 1);
    // 9) mel = relu(xsum @ proj_W), remapped to [B,T,80]
    gemm_tiled<<<dim3((MELD+63)/64, BT/64), 256>>>(xsum, proj_W, nullptr, out, BT, MELD, UU, 1, 1);
}

// round 4
// speedup vs baseline: 1.4507x; 1.4507x over previous
#include <cuda_runtime.h>
#include <math.h>

#define BB   32
#define TT   400
#define MELD 80
#define LLd  256
#define UU   512
#define MMa  200
#define U4   2048
#define U3   1536
#define BT   (BB*TT)      // 12800
#define NBLK 148
#define NTHR 1024

// ---------------- scratch ----------------
__device__ __align__(16) float g_inT [BT*MELD];
__device__ __align__(16) float g_h1  [BT*UU];
__device__ __align__(16) float g_xp  [BT*LLd];
__device__ __align__(16) float g_keys[BB*MMa*UU];
__device__ __align__(16) float g_xpart[(size_t)BT*U4];
__device__ __align__(16) float g_x   [BT*UU];
__device__ __align__(16) float g_y1  [BT*UU];
__device__ __align__(16) float g_xsum[BT*UU];
__device__ __align__(16) float g_xz  [(size_t)BT*U3];
__device__ __align__(16) float g_hstate[BB*UU];
__device__ __align__(16) float g_rec [BB*U4];
__device__ __align__(16) float g_actx[BB*2*258];   // per (b,half): mx, sum, ctx[256]
__device__ unsigned g_cnt = 0;
__device__ unsigned g_gen = 0;

__device__ __forceinline__ unsigned ld_acq(const unsigned* p) {
    unsigned v;
    asm volatile("ld.acquire.gpu.u32 %0, [%1];" : "=r"(v) : "l"(p));
    return v;
}

__device__ __forceinline__ void grid_barrier()
{
    __syncthreads();
    if (threadIdx.x == 0) {
        __threadfence();
        unsigned my   = ld_acq(&g_gen);
        unsigned prev = atomicAdd(&g_cnt, 1u);
        if (prev == NBLK - 1u) {
            atomicExch(&g_cnt, 0u);
            __threadfence();
            atomicAdd(&g_gen, 1u);
        } else {
            while (ld_acq(&g_gen) == my) { __nanosleep(32); }
        }
        __threadfence();
    }
    __syncthreads();
}

__device__ __forceinline__ float sig(float x) { return 1.f / (1.f + __expf(-x)); }
__device__ __forceinline__ float tanh_ap(float x) {
    float y; asm("tanh.approx.f32 %0, %1;" : "=f"(y) : "f"(x)); return y;
}

// ---------------- repack inputs [B,T,80] -> [T,B,80] ----------------
__global__ void repack_inputs(const float* __restrict__ in)
{
    int i = blockIdx.x * blockDim.x + threadIdx.x;
    if (i < BT * MELD) {
        int d = i % MELD;
        int r = i / MELD;          // r = t*32 + b
        int t = r >> 5, b = r & 31;
        g_inT[i] = in[((size_t)b * TT + t) * MELD + d];
    }
}

__global__ void add_kernel()
{
    int i = blockIdx.x * blockDim.x + threadIdx.x;
    if (i < BT * UU) g_xsum[i] = g_x[i] + g_y1[i];
}

// ---------------- 128x128x16 fp32 GEMM, 8x8 per thread ----------------
// Requires: M % 128 == 0, K % 16 == 0, N % 4 == 0.
__global__ void __launch_bounds__(256) gemm128(
    const float* __restrict__ A, const float* __restrict__ W,
    const float* __restrict__ bias, float* __restrict__ C,
    int N, int K, int doRelu, int remapTB)
{
    __shared__ float Asf[16*132];
    __shared__ float Bsf[16*128];
    const int tid = threadIdx.x;
    const int m0 = blockIdx.y * 128, n0 = blockIdx.x * 128;
    const int tx = tid & 15, ty = tid >> 4;
    const int ar = tid >> 2, ak = (tid & 3) * 4;
    const int br = tid >> 5, bn = (tid & 31) * 4;
    float acc[8][8] = {};

    for (int k0 = 0; k0 < K; k0 += 16) {
#pragma unroll
        for (int h = 0; h < 2; h++) {
            int row = ar + 64*h;
            float4 a4 = *(const float4*)&A[(size_t)(m0 + row) * K + k0 + ak];
            Asf[(ak+0)*132 + row] = a4.x; Asf[(ak+1)*132 + row] = a4.y;
            Asf[(ak+2)*132 + row] = a4.z; Asf[(ak+3)*132 + row] = a4.w;
        }
#pragma unroll
        for (int h = 0; h < 2; h++) {
            int gn = n0 + bn;
            float4 b4 = make_float4(0.f,0.f,0.f,0.f);
            if (gn < N) b4 = *(const float4*)&W[(size_t)(k0 + br + 8*h) * N + gn];
            *(float4*)&Bsf[(br+8*h)*128 + bn] = b4;
        }
        __syncthreads();
#pragma unroll
        for (int kk = 0; kk < 16; kk++) {
            float a[8], bv[8];
            *(float4*)&a[0]  = *(const float4*)&Asf[kk*132 + ty*8];
            *(float4*)&a[4]  = *(const float4*)&Asf[kk*132 + ty*8 + 4];
            *(float4*)&bv[0] = *(const float4*)&Bsf[kk*128 + tx*8];
            *(float4*)&bv[4] = *(const float4*)&Bsf[kk*128 + tx*8 + 4];
#pragma unroll
            for (int i = 0; i < 8; i++)
#pragma unroll
                for (int j = 0; j < 8; j++) acc[i][j] += a[i] * bv[j];
        }
        __syncthreads();
    }
#pragma unroll
    for (int i = 0; i < 8; i++) {
        int row = m0 + ty*8 + i;
#pragma unroll
        for (int h = 0; h < 2; h++) {
            int col = n0 + tx*8 + h*4;
            if (col >= N) continue;
            float4 v;
            v.x = acc[i][h*4+0]; v.y = acc[i][h*4+1];
            v.z = acc[i][h*4+2]; v.w = acc[i][h*4+3];
            if (bias) {
                float4 bb = *(const float4*)&bias[col];
                v.x += bb.x; v.y += bb.y; v.z += bb.z; v.w += bb.w;
            }
            if (doRelu) {
                v.x = fmaxf(v.x, 0.f); v.y = fmaxf(v.y, 0.f);
                v.z = fmaxf(v.z, 0.f); v.w = fmaxf(v.w, 0.f);
            }
            size_t oi;
            if (remapTB) { int t = row >> 5, b = row & 31; oi = ((size_t)b * TT + t) * N + col; }
            else         { oi = (size_t)row * N + col; }
            *(float4*)&C[oi] = v;
        }
    }
}

// ---------------- persistent attention-LSTM ----------------
// S1: blocks 0..63 attention halves; blocks 64..147 rec units (8 cols each)
// S2: blocks 0..127 (b, uq): ctx combine + ctx@K2 + rec -> gates -> h
#define SM_FLOATS 20480
__global__ void __launch_bounds__(NTHR, 1) lstm_attn(
    const float* __restrict__ attended,
    const float* __restrict__ qW, const float* __restrict__ qb,
    const float* __restrict__ vW, const float* __restrict__ vb,
    const float* __restrict__ lstmK, const float* __restrict__ lstmR)
{
    extern __shared__ float sm[];
    const int tid = threadIdx.x, bid = blockIdx.x;
    const int lane = tid & 31, wid = tid >> 5;

    // aliases (phases separated by barriers/syncs)
    float* hT    = sm;            // rec: [512][32]
    float* partR = sm + 16384;    // rec: [16][256]
    float* h_s   = sm;            // attn
    float* v_s   = sm + 512;
    float* q_s   = sm + 1024;
    float* qp    = sm + 1536;     // [8][512]
    float* sc    = sm + 5632;     // [128]
    float* red   = sm + 5760;     // [128]
    float* ctxp  = sm + 5888;     // [4][256]
    float* ctx_s = sm;            // S2
    float* zz    = sm + 256;      // [512]
    float* part2 = sm + 768;      // [8][512]

    for (int i = bid*NTHR + tid; i < BB*UU; i += NBLK*NTHR) g_hstate[i] = 0.f;
    float creg = 0.f;                     // LSTM cell state, owned per (block, tid<128)
    const float vb0 = __ldg(vb);
    grid_barrier();

    for (int t = 0; t < TT; ++t) {
        // ================= STAGE 1 =================
        if (bid < 64) {
            const int b = bid >> 1;
            const int m0 = (bid & 1) * 100;
            if (tid < UU) { h_s[tid] = __ldcg(&g_hstate[b*UU + tid]); v_s[tid] = __ldg(vW + tid); }
            __syncthreads();
            // q = h @ qW (+qb): thread (uq=128, ks=8), float4 weights
            {
                int uq = tid & 127, ks = tid >> 7;
                const float4* W4 = (const float4*)qW;
                float4 acc = make_float4(0.f,0.f,0.f,0.f);
                int k0 = ks * 64;
#pragma unroll 8
                for (int k = k0; k < k0 + 64; ++k) {
                    float4 w = __ldg(&W4[(size_t)k*128 + uq]);
                    float h = h_s[k];
                    acc.x += h*w.x; acc.y += h*w.y; acc.z += h*w.z; acc.w += h*w.w;
                }
                *(float4*)&qp[ks*512 + uq*4] = acc;
            }
            __syncthreads();
            if (tid < UU) {
                float s = __ldg(qb + tid);
#pragma unroll
                for (int j = 0; j < 8; ++j) s += qp[j*512 + tid];
                q_s[tid] = s;
            }
            __syncthreads();
            // scores for local 100 m's (tanh.approx)
            for (int m = wid; m < 100; m += 32) {
                const float* krow = g_keys + ((size_t)(b*MMa + m0 + m)) * UU;
                float acc = 0.f;
#pragma unroll
                for (int j = 0; j < 16; ++j) {
                    int u = lane + 32*j;
                    acc += v_s[u] * tanh_ap(__ldg(krow + u) + q_s[u]);
                }
#pragma unroll
                for (int o = 16; o > 0; o >>= 1) acc += __shfl_down_sync(0xffffffffu, acc, o);
                if (lane == 0) sc[m] = acc + vb0;
            }
            __syncthreads();
            // local softmax stats
            if (tid < 128) red[tid] = (tid < 100) ? sc[tid] : -1e30f;
            __syncthreads();
            for (int s = 64; s > 0; s >>= 1) { if (tid < s) red[tid] = fmaxf(red[tid], red[tid+s]); __syncthreads(); }
            float mx = red[0];
            __syncthreads();
            if (tid < 128) { float e = (tid < 100) ? __expf(sc[tid] - mx) : 0.f; sc[tid] = e; red[tid] = e; }
            __syncthreads();
            for (int s = 64; s > 0; s >>= 1) { if (tid < s) red[tid] += red[tid+s]; __syncthreads(); }
            float ssum = red[0];
            __syncthreads();
            // unnormalized partial ctx over local m's
            {
                int d = tid & 255, mp = tid >> 8;   // 4 x 25
                const float* att = attended + ((size_t)(b*MMa + m0 + mp*25)) * LLd + d;
                float acc = 0.f;
#pragma unroll
                for (int m = 0; m < 25; ++m) acc += sc[mp*25 + m] * __ldg(att + (size_t)m * LLd);
                ctxp[mp*256 + d] = acc;
            }
            __syncthreads();
            float* dst = g_actx + (size_t)(b*2 + (bid & 1)) * 258;
            if (tid < 256) dst[2 + tid] = ctxp[tid] + ctxp[256+tid] + ctxp[512+tid] + ctxp[768+tid];
            if (tid == 0) { dst[0] = mx; dst[1] = ssum; }
        } else {
            // rec blocks: load h transposed [k][b]
            for (int i4 = tid; i4 < 4096; i4 += NTHR) {
                float4 hv = __ldcg((const float4*)g_hstate + i4);
                int b = i4 >> 7, k = (i4 & 127) * 4;
                hT[(k+0)*32 + b] = hv.x; hT[(k+1)*32 + b] = hv.y;
                hT[(k+2)*32 + b] = hv.z; hT[(k+3)*32 + b] = hv.w;
            }
            __syncthreads();
            const float4* R4 = (const float4*)lstmR;     // [512][512 f4]
            for (int unit = bid - 64; unit < 256; unit += 84) {
                const int c0 = unit * 8;
                int bb = tid & 31, colq = (tid >> 5) & 1, ks = tid >> 6;   // 16 ks
                float4 acc = make_float4(0.f,0.f,0.f,0.f);
                int k0 = ks * 32;
#pragma unroll 8
                for (int k = k0; k < k0 + 32; ++k) {
                    float4 w = __ldg(&R4[(size_t)k*512 + (c0 >> 2) + colq]);
                    float h = hT[k*32 + bb];
                    acc.x += h*w.x; acc.y += h*w.y; acc.z += h*w.z; acc.w += h*w.w;
                }
                partR[ks*256 + (colq*4+0)*32 + bb] = acc.x;
                partR[ks*256 + (colq*4+1)*32 + bb] = acc.y;
                partR[ks*256 + (colq*4+2)*32 + bb] = acc.z;
                partR[ks*256 + (colq*4+3)*32 + bb] = acc.w;
                __syncthreads();
                if (tid < 256) {
                    float s = 0.f;
#pragma unroll
                    for (int j = 0; j < 16; ++j) s += partR[j*256 + tid];
                    int col = c0 + (tid >> 5), bq = tid & 31;
                    g_rec[bq*U4 + col] = s + __ldg(&g_xpart[((size_t)t*32 + bq)*U4 + col]);
                }
                __syncthreads();
            }
        }
        grid_barrier();

        // ================= STAGE 2 =================
        if (bid < 128) {
            const int b = bid >> 2, uq = bid & 3;
            const float* s1p = g_actx + (size_t)(b*2) * 258;
            const float* s2p = g_actx + (size_t)(b*2 + 1) * 258;
            float m1 = __ldcg(s1p), su1 = __ldcg(s1p + 1);
            float m2 = __ldcg(s2p), su2 = __ldcg(s2p + 1);
            float mxa = fmaxf(m1, m2);
            float w1 = __expf(m1 - mxa), w2 = __expf(m2 - mxa);
            float inv = 1.f / (w1*su1 + w2*su2);
            if (tid < 256)
                ctx_s[tid] = (w1*__ldcg(s1p + 2 + tid) + w2*__ldcg(s2p + 2 + tid)) * inv;
            __syncthreads();
            // ctx @ K2 for 512 cols (4 gates x 128 u-slice)
            {
                int colq = tid & 127, ks = tid >> 7;   // 8 ks
                int lin = colq * 4;
                int g = lin >> 7, rem = lin & 127;
                int n0 = g*UU + uq*128 + rem;
                const float4* K24 = (const float4*)(lstmK + (size_t)LLd * U4);
                float4 acc = make_float4(0.f,0.f,0.f,0.f);
                int k0 = ks * 32;
#pragma unroll 8
                for (int k = k0; k < k0 + 32; ++k) {
                    float4 w = __ldg(&K24[(size_t)k*512 + (n0 >> 2)]);
                    float c = ctx_s[k];
                    acc.x += c*w.x; acc.y += c*w.y; acc.z += c*w.z; acc.w += c*w.w;
                }
                *(float4*)&part2[ks*512 + lin] = acc;
            }
            __syncthreads();
            if (tid < UU) {
                float s = 0.f;
#pragma unroll
                for (int j = 0; j < 8; ++j) s += part2[j*512 + tid];
                int g = tid >> 7, rem = tid & 127;
                zz[tid] = s + __ldcg(&g_rec[b*U4 + g*UU + uq*128 + rem]);
            }
            __syncthreads();
            if (tid < 128) {
                int u = uq*128 + tid;
                float ig = sig(zz[tid]);
                float fg = sig(zz[128 + tid]);
                float gg = tanhf(zz[256 + tid]);
                float og = sig(zz[384 + tid]);
                float cn = fg * creg + ig * gg;
                creg = cn;
                float hn = og * tanhf(cn);
                g_hstate[b*UU + u] = hn;
                g_x[((size_t)t*32 + b)*UU + u] = hn;
            }
        }
        grid_barrier();
    }
}

// ---------------- persistent GRU (reset_after=True) ----------------
__global__ void __launch_bounds__(NTHR, 1) gru_seq(
    const float* __restrict__ R, const float* __restrict__ br,
    const float* __restrict__ xz, float* __restrict__ yout, int accumulate)
{
    __shared__ float h_s[UU];
    __shared__ float part[8*384];
    __shared__ float rr[384];
    const int tid = threadIdx.x, bid = blockIdx.x;

    for (int i = bid*NTHR + tid; i < BB*UU; i += NBLK*NTHR) g_hstate[i] = 0.f;
    grid_barrier();

    for (int t = 0; t < TT; ++t) {
        if (bid < 128) {
            const int b = bid >> 2, uq = bid & 3;
            if (tid < UU) h_s[tid] = __ldcg(&g_hstate[b*UU + tid]);
            __syncthreads();
            if (tid < 768) {
                int ks = tid / 96, colq = tid - ks * 96;   // 8 ks x 96 colq
                int lin = colq * 4;
                int g = lin >> 7, rem = lin & 127;
                int n0 = g*UU + uq*128 + rem;
                const float4* R4 = (const float4*)R;       // [512][384 f4]
                float4 acc = make_float4(0.f,0.f,0.f,0.f);
                int k0 = ks * 64;
#pragma unroll 8
                for (int k = k0; k < k0 + 64; ++k) {
                    float4 w = __ldg(&R4[(size_t)k*384 + (n0 >> 2)]);
                    float h = h_s[k];
                    acc.x += h*w.x; acc.y += h*w.y; acc.z += h*w.z; acc.w += h*w.w;
                }
                *(float4*)&part[ks*384 + lin] = acc;
            }
            __syncthreads();
            if (tid < 384) {
                float s = 0.f;
#pragma unroll
                for (int j = 0; j < 8; ++j) s += part[j*384 + tid];
                int g = tid >> 7, rem = tid & 127;
                rr[tid] = s + __ldg(br + g*UU + uq*128 + rem);
            }
            __syncthreads();
            if (tid < 128) {
                int u = uq*128 + tid;
                const float* xzr = xz + ((size_t)t*32 + b) * U3;
                float z = sig(__ldg(xzr + u)        + rr[tid]);
                float r = sig(__ldg(xzr + UU + u)   + rr[128 + tid]);
                float hh = tanhf(__ldg(xzr + 2*UU + u) + r * rr[256 + tid]);
                float hn = z * h_s[u] + (1.f - z) * hh;
                g_hstate[b*UU + u] = hn;
                size_t oi = ((size_t)t*32 + b)*UU + u;
                if (accumulate) yout[oi] += hn; else yout[oi] = hn;
            }
        }
        grid_barrier();
    }
}

// ---------------- launch ----------------
extern "C" void kernel_launch(void* const* d_in, const int* in_sizes, int n_in,
                              void* d_out, int out_size)
{
    const float* inputs   = (const float*)d_in[0];
    const float* attended = (const float*)d_in[1];
    const float* pre_W1   = (const float*)d_in[2];
    const float* pre_b1   = (const float*)d_in[3];
    const float* pre_W2   = (const float*)d_in[4];
    const float* pre_b2   = (const float*)d_in[5];
    const float* key_W    = (const float*)d_in[6];
    const float* key_b    = (const float*)d_in[7];
    const float* query_W  = (const float*)d_in[8];
    const float* query_b  = (const float*)d_in[9];
    const float* attnv_W  = (const float*)d_in[10];
    const float* attnv_b  = (const float*)d_in[11];
    const float* lstm_K   = (const float*)d_in[12];
    const float* lstm_R   = (const float*)d_in[13];
    const float* lstm_b   = (const float*)d_in[14];
    const float* gru1_K   = (const float*)d_in[15];
    const float* gru1_R   = (const float*)d_in[16];
    const float* gru1_b   = (const float*)d_in[17];
    const float* gru2_K   = (const float*)d_in[18];
    const float* gru2_R   = (const float*)d_in[19];
    const float* gru2_b   = (const float*)d_in[20];
    const float* proj_W   = (const float*)d_in[21];
    float* out = (float*)d_out;

    float *inT, *h1, *xp, *keys, *xpart, *x, *y1, *xsum, *xz;
    cudaGetSymbolAddress((void**)&inT,   g_inT);
    cudaGetSymbolAddress((void**)&h1,    g_h1);
    cudaGetSymbolAddress((void**)&xp,    g_xp);
    cudaGetSymbolAddress((void**)&keys,  g_keys);
    cudaGetSymbolAddress((void**)&xpart, g_xpart);
    cudaGetSymbolAddress((void**)&x,     g_x);
    cudaGetSymbolAddress((void**)&y1,    g_y1);
    cudaGetSymbolAddress((void**)&xsum,  g_xsum);
    cudaGetSymbolAddress((void**)&xz,    g_xz);

    cudaFuncSetAttribute(lstm_attn, cudaFuncAttributeMaxDynamicSharedMemorySize,
                         SM_FLOATS * (int)sizeof(float));

    // 1) repack inputs to [T,B,80]
    repack_inputs<<<(BT*MELD + 255)/256, 256>>>(inputs);
    // 2) prenet
    gemm128<<<dim3(4, 100), 256>>>(inT, pre_W1, pre_b1, h1, UU,  MELD, 1, 0);
    gemm128<<<dim3(2, 100), 256>>>(h1,  pre_W2, pre_b2, xp, LLd, UU,   1, 0);
    // 3) keys
    gemm128<<<dim3(4, 50),  256>>>(attended, key_W, key_b, keys, UU, LLd, 0, 0);
    // 4) LSTM input part: xp @ lstm_K[:256] + lstm_b
    gemm128<<<dim3(16, 100), 256>>>(xp, lstm_K, lstm_b, xpart, U4, LLd, 0, 0);
    // 5) attention LSTM (persistent)
    lstm_attn<<<NBLK, NTHR, SM_FLOATS*sizeof(float)>>>(
        attended, query_W, query_b, attnv_W, attnv_b, lstm_K, lstm_R);
    // 6) GRU1
    gemm128<<<dim3(12, 100), 256>>>(x, gru1_K, gru1_b, xz, U3, UU, 0, 0);
    gru_seq<<<NBLK, NTHR>>>(gru1_R, gru1_b + U3, xz, y1, 0);
    // 7) xsum = x + y1
    add_kernel<<<(BT*UU + 255)/256, 256>>>();
    // 8) GRU2 on xsum, accumulate y2 into xsum
    gemm128<<<dim3(12, 100), 256>>>(xsum, gru2_K, gru2_b, xz, U3, UU, 0, 0);
    gru_seq<<<NBLK, NTHR>>>(gru2_R, gru2_b + U3, xz, xsum, 1);
    // 9) mel = relu(xsum @ proj_W) remapped to [B,T,80]
    gemm128<<<dim3(1, 100), 256>>>(xsum, proj_W, nullptr, out, MELD, UU, 1, 1);
}

// round 5
// speedup vs baseline: 1.4536x; 1.0020x over previous
#include <cuda_runtime.h>
#include <math.h>

#define BB   32
#define TT   400
#define MELD 80
#define LLd  256
#define UU   512
#define MMa  200
#define U4   2048
#define U3   1536
#define BT   (BB*TT)      // 12800
#define NBLK 148
#define NTHR 1024

// ---------------- scratch ----------------
__device__ __align__(16) float g_inT [BT*MELD];
__device__ __align__(16) float g_h1  [BT*UU];
__device__ __align__(16) float g_xp  [BT*LLd];
__device__ __align__(16) float g_keys[BB*MMa*UU];
__device__ __align__(16) float g_xpart[(size_t)BT*U4];
__device__ __align__(16) float g_x   [BT*UU];
__device__ __align__(16) float g_y1  [BT*UU];
__device__ __align__(16) float g_xsum[BT*UU];
__device__ __align__(16) float g_xz  [(size_t)BT*U3];
__device__ __align__(16) float g_hstate[BB*UU];
__device__ __align__(16) float g_rec [BB*U4];
__device__ __align__(16) float g_actx[BB*2*258];   // per (b,half): mx, sum, ctx[256]
__device__ unsigned g_cnt = 0;
__device__ unsigned g_gen = 0;

__device__ __forceinline__ unsigned ld_acq(const unsigned* p) {
    unsigned v;
    asm volatile("ld.acquire.gpu.u32 %0, [%1];" : "=r"(v) : "l"(p));
    return v;
}

__device__ __forceinline__ void grid_barrier()
{
    __syncthreads();
    if (threadIdx.x == 0) {
        __threadfence();
        unsigned my   = ld_acq(&g_gen);
        unsigned prev = atomicAdd(&g_cnt, 1u);
        if (prev == NBLK - 1u) {
            atomicExch(&g_cnt, 0u);
            __threadfence();
            atomicAdd(&g_gen, 1u);
        } else {
            while (ld_acq(&g_gen) == my) { __nanosleep(32); }
        }
        __threadfence();
    }
    __syncthreads();
}

__device__ __forceinline__ float sig(float x) { return 1.f / (1.f + __expf(-x)); }
__device__ __forceinline__ float tanh_ap(float x) {
    float y; asm("tanh.approx.f32 %0, %1;" : "=f"(y) : "f"(x)); return y;
}

// ---------------- repack inputs [B,T,80] -> [T,B,80] ----------------
__global__ void repack_inputs(const float* __restrict__ in)
{
    int i = blockIdx.x * blockDim.x + threadIdx.x;
    if (i < BT * MELD) {
        int d = i % MELD;
        int r = i / MELD;          // r = t*32 + b
        int t = r >> 5, b = r & 31;
        g_inT[i] = in[((size_t)b * TT + t) * MELD + d];
    }
}

__global__ void add_kernel()
{
    int i = blockIdx.x * blockDim.x + threadIdx.x;
    if (i < BT * UU) g_xsum[i] = g_x[i] + g_y1[i];
}

// ---------------- 128x128x16 fp32 GEMM, 8x8 per thread ----------------
// Requires: M % 128 == 0, K % 16 == 0, N % 4 == 0.
__global__ void __launch_bounds__(256) gemm128(
    const float* __restrict__ A, const float* __restrict__ W,
    const float* __restrict__ bias, float* __restrict__ C,
    int N, int K, int doRelu, int remapTB)
{
    __shared__ float Asf[16*132];
    __shared__ float Bsf[16*128];
    const int tid = threadIdx.x;
    const int m0 = blockIdx.y * 128, n0 = blockIdx.x * 128;
    const int tx = tid & 15, ty = tid >> 4;
    const int ar = tid >> 2, ak = (tid & 3) * 4;
    const int br = tid >> 5, bn = (tid & 31) * 4;
    float acc[8][8] = {};

    for (int k0 = 0; k0 < K; k0 += 16) {
#pragma unroll
        for (int h = 0; h < 2; h++) {
            int row = ar + 64*h;
            float4 a4 = *(const float4*)&A[(size_t)(m0 + row) * K + k0 + ak];
            Asf[(ak+0)*132 + row] = a4.x; Asf[(ak+1)*132 + row] = a4.y;
            Asf[(ak+2)*132 + row] = a4.z; Asf[(ak+3)*132 + row] = a4.w;
        }
#pragma unroll
        for (int h = 0; h < 2; h++) {
            int gn = n0 + bn;
            float4 b4 = make_float4(0.f,0.f,0.f,0.f);
            if (gn < N) b4 = *(const float4*)&W[(size_t)(k0 + br + 8*h) * N + gn];
            *(float4*)&Bsf[(br+8*h)*128 + bn] = b4;
        }
        __syncthreads();
#pragma unroll
        for (int kk = 0; kk < 16; kk++) {
            float a[8], bv[8];
            *(float4*)&a[0]  = *(const float4*)&Asf[kk*132 + ty*8];
            *(float4*)&a[4]  = *(const float4*)&Asf[kk*132 + ty*8 + 4];
            *(float4*)&bv[0] = *(const float4*)&Bsf[kk*128 + tx*8];
            *(float4*)&bv[4] = *(const float4*)&Bsf[kk*128 + tx*8 + 4];
#pragma unroll
            for (int i = 0; i < 8; i++)
#pragma unroll
                for (int j = 0; j < 8; j++) acc[i][j] += a[i] * bv[j];
        }
        __syncthreads();
    }
#pragma unroll
    for (int i = 0; i < 8; i++) {
        int row = m0 + ty*8 + i;
#pragma unroll
        for (int h = 0; h < 2; h++) {
            int col = n0 + tx*8 + h*4;
            if (col >= N) continue;
            float4 v;
            v.x = acc[i][h*4+0]; v.y = acc[i][h*4+1];
            v.z = acc[i][h*4+2]; v.w = acc[i][h*4+3];
            if (bias) {
                float4 bb = *(const float4*)&bias[col];
                v.x += bb.x; v.y += bb.y; v.z += bb.z; v.w += bb.w;
            }
            if (doRelu) {
                v.x = fmaxf(v.x, 0.f); v.y = fmaxf(v.y, 0.f);
                v.z = fmaxf(v.z, 0.f); v.w = fmaxf(v.w, 0.f);
            }
            size_t oi;
            if (remapTB) { int t = row >> 5, b = row & 31; oi = ((size_t)b * TT + t) * N + col; }
            else         { oi = (size_t)row * N + col; }
            *(float4*)&C[oi] = v;
        }
    }
}

// ---------------- persistent attention-LSTM ----------------
// S1: blocks 0..63 attention halves; blocks 64..147 rec units (8 cols each)
// S2: blocks 0..127 (b, uq): ctx combine + ctx@K2 + rec -> gates -> h
#define SM_FLOATS 20480
__global__ void __launch_bounds__(NTHR, 1) lstm_attn(
    const float* __restrict__ attended,
    const float* __restrict__ qW, const float* __restrict__ qb,
    const float* __restrict__ vW, const float* __restrict__ vb,
    const float* __restrict__ lstmK, const float* __restrict__ lstmR)
{
    extern __shared__ float sm[];
    const int tid = threadIdx.x, bid = blockIdx.x;
    const int lane = tid & 31, wid = tid >> 5;

    // aliases (phases separated by barriers/syncs)
    float* hT    = sm;            // rec: [512][32]
    float* partR = sm + 16384;    // rec: [16][256]
    float* h_s   = sm;            // attn
    float* v_s   = sm + 512;
    float* q_s   = sm + 1024;
    float* qp    = sm + 1536;     // [8][512]
    float* sc    = sm + 5632;     // [128]
    float* red   = sm + 5760;     // [128]
    float* ctxp  = sm + 5888;     // [4][256]
    float* ctx_s = sm;            // S2
    float* zz    = sm + 256;      // [512]
    float* part2 = sm + 768;      // [8][512]

    for (int i = bid*NTHR + tid; i < BB*UU; i += NBLK*NTHR) g_hstate[i] = 0.f;
    float creg = 0.f;                     // LSTM cell state, owned per (block, tid<128)
    const float vb0 = __ldg(vb);
    grid_barrier();

    for (int t = 0; t < TT; ++t) {
        // ================= STAGE 1 =================
        if (bid < 64) {
            const int b = bid >> 1;
            const int m0 = (bid & 1) * 100;
            if (tid < UU) { h_s[tid] = __ldcg(&g_hstate[b*UU + tid]); v_s[tid] = __ldg(vW + tid); }
            __syncthreads();
            // q = h @ qW (+qb): thread (uq=128, ks=8), float4 weights
            {
                int uq = tid & 127, ks = tid >> 7;
                const float4* W4 = (const float4*)qW;
                float4 acc = make_float4(0.f,0.f,0.f,0.f);
                int k0 = ks * 64;
#pragma unroll 8
                for (int k = k0; k < k0 + 64; ++k) {
                    float4 w = __ldg(&W4[(size_t)k*128 + uq]);
                    float h = h_s[k];
                    acc.x += h*w.x; acc.y += h*w.y; acc.z += h*w.z; acc.w += h*w.w;
                }
                *(float4*)&qp[ks*512 + uq*4] = acc;
            }
            __syncthreads();
            if (tid < UU) {
                float s = __ldg(qb + tid);
#pragma unroll
                for (int j = 0; j < 8; ++j) s += qp[j*512 + tid];
                q_s[tid] = s;
            }
            __syncthreads();
            // scores for local 100 m's (tanh.approx)
            for (int m = wid; m < 100; m += 32) {
                const float* krow = g_keys + ((size_t)(b*MMa + m0 + m)) * UU;
                float acc = 0.f;
#pragma unroll
                for (int j = 0; j < 16; ++j) {
                    int u = lane + 32*j;
                    acc += v_s[u] * tanh_ap(__ldg(krow + u) + q_s[u]);
                }
#pragma unroll
                for (int o = 16; o > 0; o >>= 1) acc += __shfl_down_sync(0xffffffffu, acc, o);
                if (lane == 0) sc[m] = acc + vb0;
            }
            __syncthreads();
            // local softmax stats
            if (tid < 128) red[tid] = (tid < 100) ? sc[tid] : -1e30f;
            __syncthreads();
            for (int s = 64; s > 0; s >>= 1) { if (tid < s) red[tid] = fmaxf(red[tid], red[tid+s]); __syncthreads(); }
            float mx = red[0];
            __syncthreads();
            if (tid < 128) { float e = (tid < 100) ? __expf(sc[tid] - mx) : 0.f; sc[tid] = e; red[tid] = e; }
            __syncthreads();
            for (int s = 64; s > 0; s >>= 1) { if (tid < s) red[tid] += red[tid+s]; __syncthreads(); }
            float ssum = red[0];
            __syncthreads();
            // unnormalized partial ctx over local m's
            {
                int d = tid & 255, mp = tid >> 8;   // 4 x 25
                const float* att = attended + ((size_t)(b*MMa + m0 + mp*25)) * LLd + d;
                float acc = 0.f;
#pragma unroll
                for (int m = 0; m < 25; ++m) acc += sc[mp*25 + m] * __ldg(att + (size_t)m * LLd);
                ctxp[mp*256 + d] = acc;
            }
            __syncthreads();
            float* dst = g_actx + (size_t)(b*2 + (bid & 1)) * 258;
            if (tid < 256) dst[2 + tid] = ctxp[tid] + ctxp[256+tid] + ctxp[512+tid] + ctxp[768+tid];
            if (tid == 0) { dst[0] = mx; dst[1] = ssum; }
        } else {
            // rec blocks: load h transposed [k][b]
            for (int i4 = tid; i4 < 4096; i4 += NTHR) {
                float4 hv = __ldcg((const float4*)g_hstate + i4);
                int b = i4 >> 7, k = (i4 & 127) * 4;
                hT[(k+0)*32 + b] = hv.x; hT[(k+1)*32 + b] = hv.y;
                hT[(k+2)*32 + b] = hv.z; hT[(k+3)*32 + b] = hv.w;
            }
            __syncthreads();
            const float4* R4 = (const float4*)lstmR;     // [512][512 f4]
            for (int unit = bid - 64; unit < 256; unit += 84) {
                const int c0 = unit * 8;
                int bb = tid & 31, colq = (tid >> 5) & 1, ks = tid >> 6;   // 16 ks
                float4 acc = make_float4(0.f,0.f,0.f,0.f);
                int k0 = ks * 32;
#pragma unroll 8
                for (int k = k0; k < k0 + 32; ++k) {
                    float4 w = __ldg(&R4[(size_t)k*512 + (c0 >> 2) + colq]);
                    float h = hT[k*32 + bb];
                    acc.x += h*w.x; acc.y += h*w.y; acc.z += h*w.z; acc.w += h*w.w;
                }
                partR[ks*256 + (colq*4+0)*32 + bb] = acc.x;
                partR[ks*256 + (colq*4+1)*32 + bb] = acc.y;
                partR[ks*256 + (colq*4+2)*32 + bb] = acc.z;
                partR[ks*256 + (colq*4+3)*32 + bb] = acc.w;
                __syncthreads();
                if (tid < 256) {
                    float s = 0.f;
#pragma unroll
                    for (int j = 0; j < 16; ++j) s += partR[j*256 + tid];
                    int col = c0 + (tid >> 5), bq = tid & 31;
                    g_rec[bq*U4 + col] = s + __ldg(&g_xpart[((size_t)t*32 + bq)*U4 + col]);
                }
                __syncthreads();
            }
        }
        grid_barrier();

        // ================= STAGE 2 =================
        if (bid < 128) {
            const int b = bid >> 2, uq = bid & 3;
            const float* s1p = g_actx + (size_t)(b*2) * 258;
            const float* s2p = g_actx + (size_t)(b*2 + 1) * 258;
            float m1 = __ldcg(s1p), su1 = __ldcg(s1p + 1);
            float m2 = __ldcg(s2p), su2 = __ldcg(s2p + 1);
            float mxa = fmaxf(m1, m2);
            float w1 = __expf(m1 - mxa), w2 = __expf(m2 - mxa);
            float inv = 1.f / (w1*su1 + w2*su2);
            if (tid < 256)
                ctx_s[tid] = (w1*__ldcg(s1p + 2 + tid) + w2*__ldcg(s2p + 2 + tid)) * inv;
            __syncthreads();
            // ctx @ K2 for 512 cols (4 gates x 128 u-slice)
            {
                int colq = tid & 127, ks = tid >> 7;   // 8 ks
                int lin = colq * 4;
                int g = lin >> 7, rem = lin & 127;
                int n0 = g*UU + uq*128 + rem;
                const float4* K24 = (const float4*)(lstmK + (size_t)LLd * U4);
                float4 acc = make_float4(0.f,0.f,0.f,0.f);
                int k0 = ks * 32;
#pragma unroll 8
                for (int k = k0; k < k0 + 32; ++k) {
                    float4 w = __ldg(&K24[(size_t)k*512 + (n0 >> 2)]);
                    float c = ctx_s[k];
                    acc.x += c*w.x; acc.y += c*w.y; acc.z += c*w.z; acc.w += c*w.w;
                }
                *(float4*)&part2[ks*512 + lin] = acc;
            }
            __syncthreads();
            if (tid < UU) {
                float s = 0.f;
#pragma unroll
                for (int j = 0; j < 8; ++j) s += part2[j*512 + tid];
                int g = tid >> 7, rem = tid & 127;
                zz[tid] = s + __ldcg(&g_rec[b*U4 + g*UU + uq*128 + rem]);
            }
            __syncthreads();
            if (tid < 128) {
                int u = uq*128 + tid;
                float ig = sig(zz[tid]);
                float fg = sig(zz[128 + tid]);
                float gg = tanhf(zz[256 + tid]);
                float og = sig(zz[384 + tid]);
                float cn = fg * creg + ig * gg;
                creg = cn;
                float hn = og * tanhf(cn);
                g_hstate[b*UU + u] = hn;
                g_x[((size_t)t*32 + b)*UU + u] = hn;
            }
        }
        grid_barrier();
    }
}

// ---------------- persistent GRU (reset_after=True) ----------------
__global__ void __launch_bounds__(NTHR, 1) gru_seq(
    const float* __restrict__ R, const float* __restrict__ br,
    const float* __restrict__ xz, float* __restrict__ yout, int accumulate)
{
    __shared__ float h_s[UU];
    __shared__ float part[8*384];
    __shared__ float rr[384];
    const int tid = threadIdx.x, bid = blockIdx.x;

    for (int i = bid*NTHR + tid; i < BB*UU; i += NBLK*NTHR) g_hstate[i] = 0.f;
    grid_barrier();

    for (int t = 0; t < TT; ++t) {
        if (bid < 128) {
            const int b = bid >> 2, uq = bid & 3;
            if (tid < UU) h_s[tid] = __ldcg(&g_hstate[b*UU + tid]);
            __syncthreads();
            if (tid < 768) {
                int ks = tid / 96, colq = tid - ks * 96;   // 8 ks x 96 colq
                int lin = colq * 4;
                int g = lin >> 7, rem = lin & 127;
                int n0 = g*UU + uq*128 + rem;
                const float4* R4 = (const float4*)R;       // [512][384 f4]
                float4 acc = make_float4(0.f,0.f,0.f,0.f);
                int k0 = ks * 64;
#pragma unroll 8
                for (int k = k0; k < k0 + 64; ++k) {
                    float4 w = __ldg(&R4[(size_t)k*384 + (n0 >> 2)]);
                    float h = h_s[k];
                    acc.x += h*w.x; acc.y += h*w.y; acc.z += h*w.z; acc.w += h*w.w;
                }
                *(float4*)&part[ks*384 + lin] = acc;
            }
            __syncthreads();
            if (tid < 384) {
                float s = 0.f;
#pragma unroll
                for (int j = 0; j < 8; ++j) s += part[j*384 + tid];
                int g = tid >> 7, rem = tid & 127;
                rr[tid] = s + __ldg(br + g*UU + uq*128 + rem);
            }
            __syncthreads();
            if (tid < 128) {
                int u = uq*128 + tid;
                const float* xzr = xz + ((size_t)t*32 + b) * U3;
                float z = sig(__ldg(xzr + u)        + rr[tid]);
                float r = sig(__ldg(xzr + UU + u)   + rr[128 + tid]);
                float hh = tanhf(__ldg(xzr + 2*UU + u) + r * rr[256 + tid]);
                float hn = z * h_s[u] + (1.f - z) * hh;
                g_hstate[b*UU + u] = hn;
                size_t oi = ((size_t)t*32 + b)*UU + u;
                if (accumulate) yout[oi] += hn; else yout[oi] = hn;
            }
        }
        grid_barrier();
    }
}

// ---------------- launch ----------------
extern "C" void kernel_launch(void* const* d_in, const int* in_sizes, int n_in,
                              void* d_out, int out_size)
{
    const float* inputs   = (const float*)d_in[0];
    const float* attended = (const float*)d_in[1];
    const float* pre_W1   = (const float*)d_in[2];
    const float* pre_b1   = (const float*)d_in[3];
    const float* pre_W2   = (const float*)d_in[4];
    const float* pre_b2   = (const float*)d_in[5];
    const float* key_W    = (const float*)d_in[6];
    const float* key_b    = (const float*)d_in[7];
    const float* query_W  = (const float*)d_in[8];
    const float* query_b  = (const float*)d_in[9];
    const float* attnv_W  = (const float*)d_in[10];
    const float* attnv_b  = (const float*)d_in[11];
    const float* lstm_K   = (const float*)d_in[12];
    const float* lstm_R   = (const float*)d_in[13];
    const float* lstm_b   = (const float*)d_in[14];
    const float* gru1_K   = (const float*)d_in[15];
    const float* gru1_R   = (const float*)d_in[16];
    const float* gru1_b   = (const float*)d_in[17];
    const float* gru2_K   = (const float*)d_in[18];
    const float* gru2_R   = (const float*)d_in[19];
    const float* gru2_b   = (const float*)d_in[20];
    const float* proj_W   = (const float*)d_in[21];
    float* out = (float*)d_out;

    float *inT, *h1, *xp, *keys, *xpart, *x, *y1, *xsum, *xz;
    cudaGetSymbolAddress((void**)&inT,   g_inT);
    cudaGetSymbolAddress((void**)&h1,    g_h1);
    cudaGetSymbolAddress((void**)&xp,    g_xp);
    cudaGetSymbolAddress((void**)&keys,  g_keys);
    cudaGetSymbolAddress((void**)&xpart, g_xpart);
    cudaGetSymbolAddress((void**)&x,     g_x);
    cudaGetSymbolAddress((void**)&y1,    g_y1);
    cudaGetSymbolAddress((void**)&xsum,  g_xsum);
    cudaGetSymbolAddress((void**)&xz,    g_xz);

    cudaFuncSetAttribute(lstm_attn, cudaFuncAttributeMaxDynamicSharedMemorySize,
                         SM_FLOATS * (int)sizeof(float));

    // 1) repack inputs to [T,B,80]
    repack_inputs<<<(BT*MELD + 255)/256, 256>>>(inputs);
    // 2) prenet
    gemm128<<<dim3(4, 100), 256>>>(inT, pre_W1, pre_b1, h1, UU,  MELD, 1, 0);
    gemm128<<<dim3(2, 100), 256>>>(h1,  pre_W2, pre_b2, xp, LLd, UU,   1, 0);
    // 3) keys
    gemm128<<<dim3(4, 50),  256>>>(attended, key_W, key_b, keys, UU, LLd, 0, 0);
    // 4) LSTM input part: xp @ lstm_K[:256] + lstm_b
    gemm128<<<dim3(16, 100), 256>>>(xp, lstm_K, lstm_b, xpart, U4, LLd, 0, 0);
    // 5) attention LSTM (persistent)
    lstm_attn<<<NBLK, NTHR, SM_FLOATS*sizeof(float)>>>(
        attended, query_W, query_b, attnv_W, attnv_b, lstm_K, lstm_R);
    // 6) GRU1
    gemm128<<<dim3(12, 100), 256>>>(x, gru1_K, gru1_b, xz, U3, UU, 0, 0);
    gru_seq<<<NBLK, NTHR>>>(gru1_R, gru1_b + U3, xz, y1, 0);
    // 7) xsum = x + y1
    add_kernel<<<(BT*UU + 255)/256, 256>>>();
    // 8) GRU2 on xsum, accumulate y2 into xsum
    gemm128<<<dim3(12, 100), 256>>>(xsum, gru2_K, gru2_b, xz, U3, UU, 0, 0);
    gru_seq<<<NBLK, NTHR>>>(gru2_R, gru2_b + U3, xz, xsum, 1);
    // 9) mel = relu(xsum @ proj_W) remapped to [B,T,80]
    gemm128<<<dim3(1, 100), 256>>>(xsum, proj_W, nullptr, out, MELD, UU, 1, 1);
}